// round 7
// baseline (speedup 1.0000x reference)
#include <cuda_runtime.h>
#include <cuda_bf16.h>
#include <math.h>

#define L 4096
#define E 300
#define H 512
#define G 2048   // 4*H
#define TT 24
#define XW 1024  // 2*H

#define RB 32      // blocks per LSTM direction (16 hidden units each)
#define RTH 256    // threads per LSTM block
#define UPB 16     // hidden units per block
#define NGRP 4     // arrival groups per step (8 blocks per group)
#define GSTRIDE 64 // ints between group counters (256B apart)
#define STEP_INTS (NGRP * GSTRIDE)   // 256 ints per step

// ------------------------ scratch (no allocs allowed) ------------------------
__device__ float g_pre0f[(size_t)L * G];
__device__ float g_pre0b[(size_t)L * G];
__device__ float g_pre1f[(size_t)L * G];
__device__ float g_pre1b[(size_t)L * G];
__device__ float g_x1[(size_t)L * XW];
__device__ float g_x2[(size_t)L * XW];
__device__ float g_emis[(size_t)L * TT];
__device__ int   g_bar[(size_t)2 * 2 * L * STEP_INTS];  // [layer][dir][step][group]

// ------------------------ helpers ------------------------
__device__ __forceinline__ float warp_sum(float v) {
#pragma unroll
    for (int o = 16; o > 0; o >>= 1) v += __shfl_down_sync(0xffffffffu, v, o);
    return v;
}
__device__ __forceinline__ float warp_max_all(float v) {
#pragma unroll
    for (int o = 16; o > 0; o >>= 1) v = fmaxf(v, __shfl_xor_sync(0xffffffffu, v, o));
    return v;
}
__device__ __forceinline__ float sigmoidf_(float x) { return 1.0f / (1.0f + __expf(-x)); }

// ------------------------ dual GEMM: C[M,N] = A[M,K] @ B[N,K]^T + bias[N] ------------------------
__global__ __launch_bounds__(256) void gemm_bias2_kernel(
    const float* __restrict__ A, const int* __restrict__ rowmap,
    const float* __restrict__ B0, const float* __restrict__ bias0, float* __restrict__ C0,
    const float* __restrict__ B1, const float* __restrict__ bias1, float* __restrict__ C1,
    int M, int N, int K)
{
    const float* B    = blockIdx.z ? B1    : B0;
    const float* bias = blockIdx.z ? bias1 : bias0;
    float*       C    = blockIdx.z ? C1    : C0;

    __shared__ float As[8][128];
    __shared__ float Bs[8][128];

    int tid = threadIdx.x;
    int bm = blockIdx.y, bn = blockIdx.x;
    int tx = tid & 15, ty = tid >> 4;

    int loadRow = tid >> 1;            // 0..127
    int loadCol = (tid & 1) * 4;       // 0 or 4

    int aRowG = bm * 128 + loadRow;
    int aPhys = rowmap ? rowmap[aRowG] : aRowG;
    const float* Aptr = A + (size_t)aPhys * K;
    const float* Bptr = B + (size_t)(bn * 128 + loadRow) * K;

    float acc[8][8];
#pragma unroll
    for (int i = 0; i < 8; i++)
#pragma unroll
        for (int j = 0; j < 8; j++) acc[i][j] = 0.0f;

    for (int k0 = 0; k0 < K; k0 += 8) {
        int k = k0 + loadCol;
        if (k + 3 < K) {
            float4 va = *(const float4*)(Aptr + k);
            As[loadCol + 0][loadRow] = va.x;
            As[loadCol + 1][loadRow] = va.y;
            As[loadCol + 2][loadRow] = va.z;
            As[loadCol + 3][loadRow] = va.w;
            float4 vb = *(const float4*)(Bptr + k);
            Bs[loadCol + 0][loadRow] = vb.x;
            Bs[loadCol + 1][loadRow] = vb.y;
            Bs[loadCol + 2][loadRow] = vb.z;
            Bs[loadCol + 3][loadRow] = vb.w;
        } else {
#pragma unroll
            for (int i = 0; i < 4; i++) {
                int kk = k + i;
                As[loadCol + i][loadRow] = (kk < K) ? Aptr[kk] : 0.0f;
                Bs[loadCol + i][loadRow] = (kk < K) ? Bptr[kk] : 0.0f;
            }
        }
        __syncthreads();
#pragma unroll
        for (int kk = 0; kk < 8; kk++) {
            float a[8], b[8];
#pragma unroll
            for (int i = 0; i < 8; i++) a[i] = As[kk][ty * 8 + i];
#pragma unroll
            for (int j = 0; j < 8; j++) b[j] = Bs[kk][tx * 8 + j];
#pragma unroll
            for (int i = 0; i < 8; i++)
#pragma unroll
                for (int j = 0; j < 8; j++) acc[i][j] += a[i] * b[j];
        }
        __syncthreads();
    }

#pragma unroll
    for (int i = 0; i < 8; i++) {
        int row = bm * 128 + ty * 8 + i;
#pragma unroll
        for (int j = 0; j < 8; j++) {
            int col = bn * 128 + tx * 8 + j;
            C[(size_t)row * N + col] = acc[i][j] + bias[col];
        }
    }
}

// ------------------------ persistent bidirectional LSTM layer ------------------------
// 2*RB blocks; [0,RB)=forward, [RB,2RB)=backward. Each block owns 16 hidden units
// (64 gate rows = 128KB of W_hh, L1-resident after step 0).
// Sync: group arrival counters; publish = atom.add.release.gpu (cumulative, after
// __syncthreads -> covers the .cg h stores); detect = ld.acquire.gpu poll by 4 lanes.
// h exchanged through the per-t output buffer; each warp loads the full h directly
// into registers (no smem staging hop).
__global__ __launch_bounds__(RTH) void lstm_kernel(
    const float* __restrict__ pre_f, const float* __restrict__ pre_b,
    const float* __restrict__ whh_f, const float* __restrict__ whh_b,
    float* __restrict__ out, int* __restrict__ bar)
{
    int dir = (blockIdx.x >= RB) ? 1 : 0;
    int blk = blockIdx.x - dir * RB;
    const float* pre = dir ? pre_b : pre_f;
    const float* whh = dir ? whh_b : whh_f;
    int* ctr = bar + (size_t)dir * L * STEP_INTS;
    int dir_off = dir * H;
    int mygrp = blk >> 3;              // 8 blocks per group, 4 groups

    __shared__ float gates[64];
    __shared__ float pre_sh[2][64];

    int tid = threadIdx.x, lane = tid & 31, w = tid >> 5;
    int u0 = blk * UPB;

    // pre-prefetch ownership: warps 1-2 (tid 32..95), one gate row each
    int pidx = tid - 32;                                  // 0..63 when in range
    int myrow = (pidx >> 4) * H + u0 + (pidx & 15);       // valid for tid in [32,96)

    int t0 = dir ? (L - 1) : 0;
    if (tid >= 32 && tid < 96) pre_sh[0][pidx] = __ldcg(&pre[(size_t)t0 * G + myrow]);

    float c_state = 0.0f;  // meaningful for tid in [192,208)
    __syncthreads();

    for (int s = 0; s < L; s++) {
        int t = dir ? (L - 1 - s) : s;
        int tn = dir ? (t - 1) : (t + 1);   // next step's t
        int tp = dir ? (t + 1) : (t - 1);   // previous step's t

        // prefetch pre for step s+1 (in flight across the whole step)
        float pf = 0.0f;
        if (tid >= 32 && tid < 96 && s + 1 < L) pf = __ldcg(&pre[(size_t)tn * G + myrow]);

        // wait: all 4 group counters of step s-1 must reach 8 (acquire polls)
        if (s > 0) {
            if (tid < NGRP) {
                const int* addr = ctr + (size_t)(s - 1) * STEP_INTS + tid * GSTRIDE;
                int v;
                do {
                    asm volatile("ld.acquire.gpu.global.s32 %0, [%1];" : "=r"(v) : "l"(addr) : "memory");
                } while (v < 8);
            }
            __syncthreads();   // propagates the acquire ordering block-wide
        }

        // load h(prev) directly into registers: each warp loads the full 512 floats
        float4 hr[4];
        if (s == 0) {
#pragma unroll
            for (int q = 0; q < 4; q++) hr[q] = make_float4(0.f, 0.f, 0.f, 0.f);
        } else {
            const float4* hp = (const float4*)(out + (size_t)tp * XW + dir_off);
#pragma unroll
            for (int q = 0; q < 4; q++) hr[q] = __ldcg(hp + lane + q * 32);
        }

        // 64 gate rows per block: warp w handles rows lr = w*8 .. w*8+7
#pragma unroll
        for (int i = 0; i < 8; i++) {
            int lr = w * 8 + i;
            int row = (lr >> 4) * H + u0 + (lr & 15);
            const float4* wp = (const float4*)(whh + (size_t)row * H);
            float acc = 0.0f;
#pragma unroll
            for (int q = 0; q < 4; q++) {
                float4 a = wp[lane + q * 32];
                acc += a.x * hr[q].x + a.y * hr[q].y + a.z * hr[q].z + a.w * hr[q].w;
            }
            acc = warp_sum(acc);
            if (lane == 0) gates[lr] = acc + pre_sh[s & 1][lr];
        }
        __syncthreads();   // gates ready

        // activation + publish on warp 6 (tid 192..207)
        if (tid >= 192 && tid < 192 + UPB) {
            int u = tid - 192;
            float iv = sigmoidf_(gates[u]);
            float fv = sigmoidf_(gates[16 + u]);
            float gv = tanhf(gates[32 + u]);
            float ov = sigmoidf_(gates[48 + u]);
            c_state = fv * c_state + iv * gv;
            float hv = ov * tanhf(c_state);
            __stcg(out + (size_t)t * XW + dir_off + u0 + u, hv);
        }
        if (tid >= 32 && tid < 96 && s + 1 < L) pre_sh[(s + 1) & 1][pidx] = pf;
        __syncthreads();   // h stores issued; bar edge feeds release cumulativity

        if (tid == 0) {
            int old;
            asm volatile("atom.release.gpu.global.add.s32 %0, [%1], %2;"
                         : "=r"(old)
                         : "l"(ctr + (size_t)s * STEP_INTS + mygrp * GSTRIDE), "r"(1)
                         : "memory");
        }
    }
}

// ------------------------ emissions: e[L,24] = x2 @ w_out^T + b_out ------------------------
__global__ __launch_bounds__(256) void emis_kernel(
    const float* __restrict__ w_out, const float* __restrict__ b_out)
{
    int tid = threadIdx.x, lane = tid & 31, w = tid >> 5;
    int t = blockIdx.x * 8 + w;
    const float4* xp = (const float4*)(g_x2 + (size_t)t * XW);
    float4 xr[8];
#pragma unroll
    for (int q = 0; q < 8; q++) xr[q] = xp[lane + q * 32];
    for (int j = 0; j < TT; j++) {
        const float4* wp = (const float4*)(w_out + (size_t)j * XW);
        float acc = 0.0f;
#pragma unroll
        for (int q = 0; q < 8; q++) {
            float4 wv = wp[lane + q * 32];
            acc += xr[q].x * wv.x + xr[q].y * wv.y + xr[q].z * wv.z + xr[q].w * wv.w;
        }
        acc = warp_sum(acc);
        if (lane == 0) g_emis[(size_t)t * TT + j] = acc + b_out[j];
    }
}

// ------------------------ CRF NLL ------------------------
__global__ __launch_bounds__(768) void crf_kernel(
    const float* __restrict__ start_trans, const float* __restrict__ end_trans,
    const float* __restrict__ trans, const int* __restrict__ tags,
    float* __restrict__ outp)
{
    __shared__ float trans_sh[TT * 25];
    __shared__ float alpha[2][TT];
    __shared__ float red[24];
    __shared__ float num_sh;

    int tid = threadIdx.x, lane = tid & 31, w = tid >> 5;

    // numerator (parallel part)
    float p = 0.0f;
    for (int t = tid; t < L; t += 768) p += g_emis[(size_t)t * TT + tags[t]];
    for (int t = tid; t < L - 1; t += 768) p += trans[tags[t] * TT + tags[t + 1]];
    p = warp_sum(p);
    if (lane == 0) red[w] = p;

    for (int i = tid; i < TT * TT; i += 768)
        trans_sh[(i / TT) * 25 + (i % TT)] = trans[i];
    if (tid < TT) alpha[0][tid] = start_trans[tid] + g_emis[tid];
    __syncthreads();

    if (w == 0) {
        float q = (lane < 24) ? red[lane] : 0.0f;
        q = warp_sum(q);
        if (lane == 0) num_sh = q + start_trans[tags[0]] + end_trans[tags[L - 1]];
    }
    __syncthreads();

    // forward scan: warp j computes alpha'[j] = logsumexp_i(alpha[i] + trans[i][j]) + e[t][j]
    for (int t = 1; t < L; t++) {
        int cur = t & 1, prv = cur ^ 1;
        if (w < TT) {
            float v = (lane < TT) ? alpha[prv][lane] + trans_sh[lane * 25 + w] : -1e30f;
            float m = warp_max_all(v);
            float e = (lane < TT) ? __expf(v - m) : 0.0f;
            float ssum = warp_sum(e);
            if (lane == 0) alpha[cur][w] = m + logf(ssum) + g_emis[(size_t)t * TT + w];
        }
        __syncthreads();
    }

    if (tid < 32) {
        int tl = (L - 1) & 1;
        float v = (lane < TT) ? alpha[tl][lane] + end_trans[lane] : -1e30f;
        float m = warp_max_all(v);
        float e = (lane < TT) ? __expf(v - m) : 0.0f;
        float ssum = warp_sum(e);
        if (lane == 0) outp[0] = (m + logf(ssum)) - num_sh;
    }
}

// ------------------------ launch ------------------------
extern "C" void kernel_launch(void* const* d_in, const int* in_sizes, int n_in,
                              void* d_out, int out_size)
{
    const float* emb       = (const float*)d_in[0];
    const float* w_ih_l0f  = (const float*)d_in[1];
    const float* w_hh_l0f  = (const float*)d_in[2];
    const float* b_l0f     = (const float*)d_in[3];
    const float* w_ih_l0b  = (const float*)d_in[4];
    const float* w_hh_l0b  = (const float*)d_in[5];
    const float* b_l0b     = (const float*)d_in[6];
    const float* w_ih_l1f  = (const float*)d_in[7];
    const float* w_hh_l1f  = (const float*)d_in[8];
    const float* b_l1f     = (const float*)d_in[9];
    const float* w_ih_l1b  = (const float*)d_in[10];
    const float* w_hh_l1b  = (const float*)d_in[11];
    const float* b_l1b     = (const float*)d_in[12];
    const float* w_out     = (const float*)d_in[13];
    const float* b_out     = (const float*)d_in[14];
    const float* start_tr  = (const float*)d_in[15];
    const float* end_tr    = (const float*)d_in[16];
    const float* trans     = (const float*)d_in[17];
    const int*   sentence  = (const int*)d_in[18];
    const int*   tags      = (const int*)d_in[19];
    float* outp = (float*)d_out;

    float *pre0f, *pre0b, *pre1f, *pre1b, *x1, *x2;
    int* bar;
    cudaGetSymbolAddress((void**)&pre0f, g_pre0f);
    cudaGetSymbolAddress((void**)&pre0b, g_pre0b);
    cudaGetSymbolAddress((void**)&pre1f, g_pre1f);
    cudaGetSymbolAddress((void**)&pre1b, g_pre1b);
    cudaGetSymbolAddress((void**)&x1, g_x1);
    cudaGetSymbolAddress((void**)&x2, g_x2);
    cudaGetSymbolAddress((void**)&bar, g_bar);

    cudaMemsetAsync(bar, 0, (size_t)2 * 2 * L * STEP_INTS * sizeof(int));

    dim3 ggrid(G / 128, L / 128, 2);  // (16, 32, 2)

    // layer 0 input pre-activations (with embedding gather), both directions
    gemm_bias2_kernel<<<ggrid, 256>>>(emb, sentence,
                                      w_ih_l0f, b_l0f, pre0f,
                                      w_ih_l0b, b_l0b, pre0b, L, G, E);

    // layer 0 recurrence -> x1 = concat(hf, hb)
    lstm_kernel<<<2 * RB, RTH>>>(pre0f, pre0b, w_hh_l0f, w_hh_l0b, x1, bar);

    // layer 1 input pre-activations
    gemm_bias2_kernel<<<ggrid, 256>>>(x1, nullptr,
                                      w_ih_l1f, b_l1f, pre1f,
                                      w_ih_l1b, b_l1b, pre1b, L, G, XW);

    // layer 1 recurrence -> x2
    lstm_kernel<<<2 * RB, RTH>>>(pre1f, pre1b, w_hh_l1f, w_hh_l1b, x2,
                                 bar + (size_t)2 * L * STEP_INTS);

    // emissions + CRF
    emis_kernel<<<L / 8, 256>>>(w_out, b_out);
    crf_kernel<<<1, 768>>>(start_tr, end_tr, trans, tags, outp);
}

// round 8
// speedup vs baseline: 1.0523x; 1.0523x over previous
#include <cuda_runtime.h>
#include <cuda_bf16.h>
#include <math.h>

#define L 4096
#define E 300
#define H 512
#define G 2048   // 4*H
#define TT 24
#define XW 1024  // 2*H

#define RB 64      // blocks per LSTM direction (8 hidden units each, 1 per warp)
#define RTH 256    // threads per LSTM block (8 warps)
#define NGRP 4     // arrival groups (16 blocks each)
#define GSTRIDE 256            // ints between group counters (1KB apart -> distinct L2 slices)
#define STEP_INTS (NGRP * GSTRIDE)

// ------------------------ scratch (no allocs allowed) ------------------------
__device__ float g_pre0f[(size_t)L * G];
__device__ float g_pre0b[(size_t)L * G];
__device__ float g_pre1f[(size_t)L * G];
__device__ float g_pre1b[(size_t)L * G];
__device__ float g_x1[(size_t)L * XW];
__device__ float g_x2[(size_t)L * XW];
__device__ float g_emis[(size_t)L * TT];
__device__ int   g_bar[(size_t)2 * 2 * L * STEP_INTS];  // [layer][dir][step][group]

// ------------------------ helpers ------------------------
__device__ __forceinline__ float warp_sum(float v) {
#pragma unroll
    for (int o = 16; o > 0; o >>= 1) v += __shfl_down_sync(0xffffffffu, v, o);
    return v;
}
__device__ __forceinline__ float warp_max_all(float v) {
#pragma unroll
    for (int o = 16; o > 0; o >>= 1) v = fmaxf(v, __shfl_xor_sync(0xffffffffu, v, o));
    return v;
}
__device__ __forceinline__ float sigmoidf_(float x) { return 1.0f / (1.0f + __expf(-x)); }

// ------------------------ dual GEMM: C[M,N] = A[M,K] @ B[N,K]^T + bias[N] ------------------------
__global__ __launch_bounds__(256) void gemm_bias2_kernel(
    const float* __restrict__ A, const int* __restrict__ rowmap,
    const float* __restrict__ B0, const float* __restrict__ bias0, float* __restrict__ C0,
    const float* __restrict__ B1, const float* __restrict__ bias1, float* __restrict__ C1,
    int M, int N, int K)
{
    const float* B    = blockIdx.z ? B1    : B0;
    const float* bias = blockIdx.z ? bias1 : bias0;
    float*       C    = blockIdx.z ? C1    : C0;

    __shared__ float As[8][128];
    __shared__ float Bs[8][128];

    int tid = threadIdx.x;
    int bm = blockIdx.y, bn = blockIdx.x;
    int tx = tid & 15, ty = tid >> 4;

    int loadRow = tid >> 1;            // 0..127
    int loadCol = (tid & 1) * 4;       // 0 or 4

    int aRowG = bm * 128 + loadRow;
    int aPhys = rowmap ? rowmap[aRowG] : aRowG;
    const float* Aptr = A + (size_t)aPhys * K;
    const float* Bptr = B + (size_t)(bn * 128 + loadRow) * K;

    float acc[8][8];
#pragma unroll
    for (int i = 0; i < 8; i++)
#pragma unroll
        for (int j = 0; j < 8; j++) acc[i][j] = 0.0f;

    for (int k0 = 0; k0 < K; k0 += 8) {
        int k = k0 + loadCol;
        if (k + 3 < K) {
            float4 va = *(const float4*)(Aptr + k);
            As[loadCol + 0][loadRow] = va.x;
            As[loadCol + 1][loadRow] = va.y;
            As[loadCol + 2][loadRow] = va.z;
            As[loadCol + 3][loadRow] = va.w;
            float4 vb = *(const float4*)(Bptr + k);
            Bs[loadCol + 0][loadRow] = vb.x;
            Bs[loadCol + 1][loadRow] = vb.y;
            Bs[loadCol + 2][loadRow] = vb.z;
            Bs[loadCol + 3][loadRow] = vb.w;
        } else {
#pragma unroll
            for (int i = 0; i < 4; i++) {
                int kk = k + i;
                As[loadCol + i][loadRow] = (kk < K) ? Aptr[kk] : 0.0f;
                Bs[loadCol + i][loadRow] = (kk < K) ? Bptr[kk] : 0.0f;
            }
        }
        __syncthreads();
#pragma unroll
        for (int kk = 0; kk < 8; kk++) {
            float a[8], b[8];
#pragma unroll
            for (int i = 0; i < 8; i++) a[i] = As[kk][ty * 8 + i];
#pragma unroll
            for (int j = 0; j < 8; j++) b[j] = Bs[kk][tx * 8 + j];
#pragma unroll
            for (int i = 0; i < 8; i++)
#pragma unroll
                for (int j = 0; j < 8; j++) acc[i][j] += a[i] * b[j];
        }
        __syncthreads();
    }

#pragma unroll
    for (int i = 0; i < 8; i++) {
        int row = bm * 128 + ty * 8 + i;
#pragma unroll
        for (int j = 0; j < 8; j++) {
            int col = bn * 128 + tx * 8 + j;
            C[(size_t)row * N + col] = acc[i][j] + bias[col];
        }
    }
}

// ------------------------ persistent bidirectional LSTM layer ------------------------
// 2*RB blocks; [0,RB)=forward, [RB,2RB)=backward. WARP = one hidden unit:
// warp w of block blk owns unit u = blk*8+w and all 4 of its gate rows (8KB of W_hh).
// Step flow (ONE __syncthreads per step):
//   - issue pre[t+1] prefetch (reg), then lanes 0-3 acquire-poll the 4 group counters
//     of step s-1; __syncwarp reconverges; warp proceeds independently.
//   - warp loads full h(prev) to registers (.cg, L2 is the coherence point).
//   - 4 gate dot-products per lane, 4 warp reductions, lane0 does activation +
//     c-state update + .cg h store + __threadfence.
//   - __syncthreads, then tid0 release-atomicAdd on this block's group counter.
__global__ __launch_bounds__(RTH) void lstm_kernel(
    const float* __restrict__ pre_f, const float* __restrict__ pre_b,
    const float* __restrict__ whh_f, const float* __restrict__ whh_b,
    float* __restrict__ out, int* __restrict__ bar)
{
    int dir = (blockIdx.x >= RB) ? 1 : 0;
    int blk = blockIdx.x - dir * RB;
    const float* pre = dir ? pre_b : pre_f;
    const float* whh = dir ? whh_b : whh_f;
    int* ctr = bar + (size_t)dir * L * STEP_INTS;
    int dir_off = dir * H;
    int mygrp = blk & 3;                // 16 blocks per group

    int tid = threadIdx.x, lane = tid & 31, w = tid >> 5;
    int u = blk * 8 + w;                // hidden unit owned by this warp

    // weight row pointers for the 4 gates of unit u (lane-sliced float4, stride 128 floats)
    const float4* wp0 = (const float4*)(whh + (size_t)(0 * H + u) * H) + lane;
    const float4* wp1 = (const float4*)(whh + (size_t)(1 * H + u) * H) + lane;
    const float4* wp2 = (const float4*)(whh + (size_t)(2 * H + u) * H) + lane;
    const float4* wp3 = (const float4*)(whh + (size_t)(3 * H + u) * H) + lane;

    int t0 = dir ? (L - 1) : 0;
    // current pre values: lane g (g<4) holds pre[t][g*H + u]
    float pcur = (lane < 4) ? __ldcg(&pre[(size_t)t0 * G + lane * H + u]) : 0.0f;

    float c_state = 0.0f;  // meaningful at lane 0

    for (int s = 0; s < L; s++) {
        int t = dir ? (L - 1 - s) : s;
        int tn = dir ? (t - 1) : (t + 1);   // next step's t
        int tp = dir ? (t + 1) : (t - 1);   // previous step's t

        // prefetch pre for step s+1 (in flight during the spin)
        float pnext = 0.0f;
        if (lane < 4 && s + 1 < L) pnext = __ldcg(&pre[(size_t)tn * G + lane * H + u]);

        // per-warp spin: lanes 0-3 each acquire-poll one group counter of step s-1
        if (s > 0) {
            if (lane < NGRP) {
                const int* addr = ctr + (size_t)(s - 1) * STEP_INTS + lane * GSTRIDE;
                int v;
                do {
                    asm volatile("ld.acquire.gpu.global.s32 %0, [%1];" : "=r"(v) : "l"(addr) : "memory");
                } while (v < RB / NGRP);
            }
            __syncwarp();
        }

        // load h(prev) directly into registers (full 512 floats per warp)
        float4 h0, h1, h2, h3;
        if (s == 0) {
            h0 = h1 = h2 = h3 = make_float4(0.f, 0.f, 0.f, 0.f);
        } else {
            const float4* hp = (const float4*)(out + (size_t)tp * XW + dir_off) + lane;
            h0 = __ldcg(hp);
            h1 = __ldcg(hp + 32);
            h2 = __ldcg(hp + 64);
            h3 = __ldcg(hp + 96);
        }

        // 4 gate dot-products (64 FMA per lane)
        float a0 = 0.f, a1 = 0.f, a2 = 0.f, a3 = 0.f;
        {
            float4 q;
            q = wp0[0];  a0 += q.x*h0.x + q.y*h0.y + q.z*h0.z + q.w*h0.w;
            q = wp0[32]; a0 += q.x*h1.x + q.y*h1.y + q.z*h1.z + q.w*h1.w;
            q = wp0[64]; a0 += q.x*h2.x + q.y*h2.y + q.z*h2.z + q.w*h2.w;
            q = wp0[96]; a0 += q.x*h3.x + q.y*h3.y + q.z*h3.z + q.w*h3.w;
            q = wp1[0];  a1 += q.x*h0.x + q.y*h0.y + q.z*h0.z + q.w*h0.w;
            q = wp1[32]; a1 += q.x*h1.x + q.y*h1.y + q.z*h1.z + q.w*h1.w;
            q = wp1[64]; a1 += q.x*h2.x + q.y*h2.y + q.z*h2.z + q.w*h2.w;
            q = wp1[96]; a1 += q.x*h3.x + q.y*h3.y + q.z*h3.z + q.w*h3.w;
            q = wp2[0];  a2 += q.x*h0.x + q.y*h0.y + q.z*h0.z + q.w*h0.w;
            q = wp2[32]; a2 += q.x*h1.x + q.y*h1.y + q.z*h1.z + q.w*h1.w;
            q = wp2[64]; a2 += q.x*h2.x + q.y*h2.y + q.z*h2.z + q.w*h2.w;
            q = wp2[96]; a2 += q.x*h3.x + q.y*h3.y + q.z*h3.z + q.w*h3.w;
            q = wp3[0];  a3 += q.x*h0.x + q.y*h0.y + q.z*h0.z + q.w*h0.w;
            q = wp3[32]; a3 += q.x*h1.x + q.y*h1.y + q.z*h1.z + q.w*h1.w;
            q = wp3[64]; a3 += q.x*h2.x + q.y*h2.y + q.z*h2.z + q.w*h2.w;
            q = wp3[96]; a3 += q.x*h3.x + q.y*h3.y + q.z*h3.z + q.w*h3.w;
        }
        a0 = warp_sum(a0);
        a1 = warp_sum(a1);
        a2 = warp_sum(a2);
        a3 = warp_sum(a3);

        // gate pre-activations live on lanes 0-3 of pcur
        float p0 = __shfl_sync(0xffffffffu, pcur, 0);
        float p1 = __shfl_sync(0xffffffffu, pcur, 1);
        float p2 = __shfl_sync(0xffffffffu, pcur, 2);
        float p3 = __shfl_sync(0xffffffffu, pcur, 3);

        if (lane == 0) {
            float iv = sigmoidf_(a0 + p0);
            float fv = sigmoidf_(a1 + p1);
            float gv = tanhf(a2 + p2);
            float ov = sigmoidf_(a3 + p3);
            c_state = fv * c_state + iv * gv;
            float hv = ov * tanhf(c_state);
            __stcg(out + (size_t)t * XW + dir_off + u, hv);
            __threadfence();
        }
        pcur = pnext;

        __syncthreads();   // all 8 warps published (stores + fences before this edge)

        if (tid == 0) {
            int old;
            asm volatile("atom.release.gpu.global.add.s32 %0, [%1], %2;"
                         : "=r"(old)
                         : "l"(ctr + (size_t)s * STEP_INTS + mygrp * GSTRIDE), "r"(1)
                         : "memory");
        }
    }
}

// ------------------------ emissions: e[L,24] = x2 @ w_out^T + b_out ------------------------
__global__ __launch_bounds__(256) void emis_kernel(
    const float* __restrict__ w_out, const float* __restrict__ b_out)
{
    int tid = threadIdx.x, lane = tid & 31, w = tid >> 5;
    int t = blockIdx.x * 8 + w;
    const float4* xp = (const float4*)(g_x2 + (size_t)t * XW);
    float4 xr[8];
#pragma unroll
    for (int q = 0; q < 8; q++) xr[q] = xp[lane + q * 32];
    for (int j = 0; j < TT; j++) {
        const float4* wp = (const float4*)(w_out + (size_t)j * XW);
        float acc = 0.0f;
#pragma unroll
        for (int q = 0; q < 8; q++) {
            float4 wv = wp[lane + q * 32];
            acc += xr[q].x * wv.x + xr[q].y * wv.y + xr[q].z * wv.z + xr[q].w * wv.w;
        }
        acc = warp_sum(acc);
        if (lane == 0) g_emis[(size_t)t * TT + j] = acc + b_out[j];
    }
}

// ------------------------ CRF NLL ------------------------
__global__ __launch_bounds__(768) void crf_kernel(
    const float* __restrict__ start_trans, const float* __restrict__ end_trans,
    const float* __restrict__ trans, const int* __restrict__ tags,
    float* __restrict__ outp)
{
    __shared__ float trans_sh[TT * 25];
    __shared__ float alpha[2][TT];
    __shared__ float red[24];
    __shared__ float num_sh;

    int tid = threadIdx.x, lane = tid & 31, w = tid >> 5;

    // numerator (parallel part)
    float p = 0.0f;
    for (int t = tid; t < L; t += 768) p += g_emis[(size_t)t * TT + tags[t]];
    for (int t = tid; t < L - 1; t += 768) p += trans[tags[t] * TT + tags[t + 1]];
    p = warp_sum(p);
    if (lane == 0) red[w] = p;

    for (int i = tid; i < TT * TT; i += 768)
        trans_sh[(i / TT) * 25 + (i % TT)] = trans[i];
    if (tid < TT) alpha[0][tid] = start_trans[tid] + g_emis[tid];
    __syncthreads();

    if (w == 0) {
        float q = (lane < 24) ? red[lane] : 0.0f;
        q = warp_sum(q);
        if (lane == 0) num_sh = q + start_trans[tags[0]] + end_trans[tags[L - 1]];
    }
    __syncthreads();

    // forward scan: warp j computes alpha'[j] = logsumexp_i(alpha[i] + trans[i][j]) + e[t][j]
    for (int t = 1; t < L; t++) {
        int cur = t & 1, prv = cur ^ 1;
        if (w < TT) {
            float v = (lane < TT) ? alpha[prv][lane] + trans_sh[lane * 25 + w] : -1e30f;
            float m = warp_max_all(v);
            float e = (lane < TT) ? __expf(v - m) : 0.0f;
            float ssum = warp_sum(e);
            if (lane == 0) alpha[cur][w] = m + logf(ssum) + g_emis[(size_t)t * TT + w];
        }
        __syncthreads();
    }

    if (tid < 32) {
        int tl = (L - 1) & 1;
        float v = (lane < TT) ? alpha[tl][lane] + end_trans[lane] : -1e30f;
        float m = warp_max_all(v);
        float e = (lane < TT) ? __expf(v - m) : 0.0f;
        float ssum = warp_sum(e);
        if (lane == 0) outp[0] = (m + logf(ssum)) - num_sh;
    }
}

// ------------------------ launch ------------------------
extern "C" void kernel_launch(void* const* d_in, const int* in_sizes, int n_in,
                              void* d_out, int out_size)
{
    const float* emb       = (const float*)d_in[0];
    const float* w_ih_l0f  = (const float*)d_in[1];
    const float* w_hh_l0f  = (const float*)d_in[2];
    const float* b_l0f     = (const float*)d_in[3];
    const float* w_ih_l0b  = (const float*)d_in[4];
    const float* w_hh_l0b  = (const float*)d_in[5];
    const float* b_l0b     = (const float*)d_in[6];
    const float* w_ih_l1f  = (const float*)d_in[7];
    const float* w_hh_l1f  = (const float*)d_in[8];
    const float* b_l1f     = (const float*)d_in[9];
    const float* w_ih_l1b  = (const float*)d_in[10];
    const float* w_hh_l1b  = (const float*)d_in[11];
    const float* b_l1b     = (const float*)d_in[12];
    const float* w_out     = (const float*)d_in[13];
    const float* b_out     = (const float*)d_in[14];
    const float* start_tr  = (const float*)d_in[15];
    const float* end_tr    = (const float*)d_in[16];
    const float* trans     = (const float*)d_in[17];
    const int*   sentence  = (const int*)d_in[18];
    const int*   tags      = (const int*)d_in[19];
    float* outp = (float*)d_out;

    float *pre0f, *pre0b, *pre1f, *pre1b, *x1, *x2;
    int* bar;
    cudaGetSymbolAddress((void**)&pre0f, g_pre0f);
    cudaGetSymbolAddress((void**)&pre0b, g_pre0b);
    cudaGetSymbolAddress((void**)&pre1f, g_pre1f);
    cudaGetSymbolAddress((void**)&pre1b, g_pre1b);
    cudaGetSymbolAddress((void**)&x1, g_x1);
    cudaGetSymbolAddress((void**)&x2, g_x2);
    cudaGetSymbolAddress((void**)&bar, g_bar);

    cudaMemsetAsync(bar, 0, (size_t)2 * 2 * L * STEP_INTS * sizeof(int));

    dim3 ggrid(G / 128, L / 128, 2);  // (16, 32, 2)

    // layer 0 input pre-activations (with embedding gather), both directions
    gemm_bias2_kernel<<<ggrid, 256>>>(emb, sentence,
                                      w_ih_l0f, b_l0f, pre0f,
                                      w_ih_l0b, b_l0b, pre0b, L, G, E);

    // layer 0 recurrence -> x1 = concat(hf, hb)
    lstm_kernel<<<2 * RB, RTH>>>(pre0f, pre0b, w_hh_l0f, w_hh_l0b, x1, bar);

    // layer 1 input pre-activations
    gemm_bias2_kernel<<<ggrid, 256>>>(x1, nullptr,
                                      w_ih_l1f, b_l1f, pre1f,
                                      w_ih_l1b, b_l1b, pre1b, L, G, XW);

    // layer 1 recurrence -> x2
    lstm_kernel<<<2 * RB, RTH>>>(pre1f, pre1b, w_hh_l1f, w_hh_l1b, x2,
                                 bar + (size_t)2 * L * STEP_INTS);

    // emissions + CRF
    emis_kernel<<<L / 8, 256>>>(w_out, b_out);
    crf_kernel<<<1, 768>>>(start_tr, end_tr, trans, tags, outp);
}